// round 1
// baseline (speedup 1.0000x reference)
#include <cuda_runtime.h>
#include <cuda_bf16.h>
#include <cfloat>

// Problem shapes (fixed by setup_inputs)
#define BATCH 4
#define NPTS 4096
#define NUP 16384
#define CDIM 64      // C == DIM == 64
#define KNN 3
#define EPSV 1e-6f

// Scratch (no cudaMalloc allowed)
__device__ float  g_G[BATCH * NPTS * CDIM];     // projected features F@W + b  (4 MB)
__device__ float4 g_pos4[BATCH * NPTS];         // (x, y, z, |p|^2)            (256 KB)

// ---------------------------------------------------------------------------
// Prep: pack pos into float4 with squared norm
// ---------------------------------------------------------------------------
__global__ void prep_pos_kernel(const float* __restrict__ pos) {
    int i = blockIdx.x * blockDim.x + threadIdx.x;
    if (i < BATCH * NPTS) {
        float x = pos[3 * i + 0];
        float y = pos[3 * i + 1];
        float z = pos[3 * i + 2];
        float n = x * x + y * y + z * z;
        g_pos4[i] = make_float4(x, y, z, n);
    }
}

// ---------------------------------------------------------------------------
// Projection: G[row][d] = b[d] + sum_c feature[row][c] * W[c][d]
// blockDim = 64 (one thread per output column d), 32 rows per block.
// W column kept in registers; feature rows staged in smem (broadcast reads).
// ---------------------------------------------------------------------------
#define PROJ_ROWS 32

__global__ __launch_bounds__(64) void proj_kernel(
    const float* __restrict__ feature,
    const float* __restrict__ W,
    const float* __restrict__ bias)
{
    __shared__ float frow[PROJ_ROWS * CDIM];
    const int d = threadIdx.x;
    const int row0 = blockIdx.x * PROJ_ROWS;

    // W column into registers (coalesced across threads)
    float wcol[CDIM];
#pragma unroll
    for (int k = 0; k < CDIM; k++) wcol[k] = __ldg(&W[k * CDIM + d]);
    const float bd = __ldg(&bias[d]);

    // Stage 32 feature rows
    const float* fsrc = feature + (size_t)row0 * CDIM;
    for (int i = threadIdx.x; i < PROJ_ROWS * CDIM; i += 64)
        frow[i] = fsrc[i];
    __syncthreads();

    for (int r = 0; r < PROJ_ROWS; r++) {
        // 4 partial accumulators to break the FFMA dependency chain
        float a0 = bd, a1 = 0.f, a2 = 0.f, a3 = 0.f;
        const float* fr = &frow[r * CDIM];
#pragma unroll
        for (int k = 0; k < CDIM; k += 4) {
            a0 = fmaf(fr[k + 0], wcol[k + 0], a0);
            a1 = fmaf(fr[k + 1], wcol[k + 1], a1);
            a2 = fmaf(fr[k + 2], wcol[k + 2], a2);
            a3 = fmaf(fr[k + 3], wcol[k + 3], a3);
        }
        g_G[(size_t)(row0 + r) * CDIM + d] = (a0 + a1) + (a2 + a3);
    }
}

// ---------------------------------------------------------------------------
// Main: per-query brute-force 3-NN over smem pos tile + weighted gather of G.
// One thread per query. s = |p|^2 - 2 q.p  (order-equivalent to d^2; add |q|^2
// back after selection for the weights).
// ---------------------------------------------------------------------------
#define QPB 128         // queries (threads) per block
#define CHUNK 2048      // candidates per smem tile (32 KB)

__global__ __launch_bounds__(QPB) void knn_apply_kernel(
    const float* __restrict__ pos_up,
    float* __restrict__ out)
{
    __shared__ float4 tile[CHUNK];

    const int b = blockIdx.y;
    const int q = blockIdx.x * QPB + threadIdx.x;

    const float* pu = pos_up + ((size_t)b * NUP + q) * 3;
    const float qx = pu[0], qy = pu[1], qz = pu[2];
    const float qn = qx * qx + qy * qy + qz * qz;
    const float qx2 = -2.0f * qx, qy2 = -2.0f * qy, qz2 = -2.0f * qz;

    float d0 = FLT_MAX, d1 = FLT_MAX, d2 = FLT_MAX;
    int   i0 = 0, i1 = 0, i2 = 0;

    const float4* src = g_pos4 + b * NPTS;

    for (int c0 = 0; c0 < NPTS; c0 += CHUNK) {
        __syncthreads();
        for (int i = threadIdx.x; i < CHUNK; i += QPB)
            tile[i] = src[c0 + i];
        __syncthreads();

#pragma unroll 8
        for (int j = 0; j < CHUNK; j++) {
            float4 p = tile[j];
            float s = fmaf(qx2, p.x, fmaf(qy2, p.y, fmaf(qz2, p.z, p.w)));
            if (s < d2) {
                int idx = c0 + j;
                if (s < d1) {
                    d2 = d1; i2 = i1;
                    if (s < d0) { d1 = d0; i1 = i0; d0 = s; i0 = idx; }
                    else        { d1 = s;  i1 = idx; }
                } else {
                    d2 = s; i2 = idx;
                }
            }
        }
    }

    // weights: w = 1/(d2_actual + eps), normalized
    float e0 = (d0 + qn) + EPSV;
    float e1 = (d1 + qn) + EPSV;
    float e2 = (d2 + qn) + EPSV;
    float w0 = 1.0f / e0;
    float w1 = 1.0f / e1;
    float w2 = 1.0f / e2;
    float wsum = w0 + w1 + w2;
    float inv = 1.0f / wsum;
    float wn0 = w0 * inv, wn1 = w1 * inv, wn2 = w2 * inv;

    // gather 3 projected rows, blend, relu, store
    const float4* G4 = reinterpret_cast<const float4*>(g_G);
    const float4* r0 = G4 + ((size_t)(b * NPTS + i0)) * (CDIM / 4);
    const float4* r1 = G4 + ((size_t)(b * NPTS + i1)) * (CDIM / 4);
    const float4* r2 = G4 + ((size_t)(b * NPTS + i2)) * (CDIM / 4);
    float4* out4 = reinterpret_cast<float4*>(out) + ((size_t)b * NUP + q) * (CDIM / 4);

#pragma unroll
    for (int t = 0; t < CDIM / 4; t++) {
        float4 a = __ldg(&r0[t]);
        float4 c = __ldg(&r1[t]);
        float4 e = __ldg(&r2[t]);
        float4 o;
        o.x = fmaxf(0.f, fmaf(wn0, a.x, fmaf(wn1, c.x, wn2 * e.x)));
        o.y = fmaxf(0.f, fmaf(wn0, a.y, fmaf(wn1, c.y, wn2 * e.y)));
        o.z = fmaxf(0.f, fmaf(wn0, a.z, fmaf(wn1, c.z, wn2 * e.z)));
        o.w = fmaxf(0.f, fmaf(wn0, a.w, fmaf(wn1, c.w, wn2 * e.w)));
        out4[t] = o;
    }
}

// ---------------------------------------------------------------------------
extern "C" void kernel_launch(void* const* d_in, const int* in_sizes, int n_in,
                              void* d_out, int out_size)
{
    const float* feature = (const float*)d_in[0];   // (4, 4096, 64)
    const float* pos     = (const float*)d_in[1];   // (4, 4096, 3)
    const float* pos_up  = (const float*)d_in[2];   // (4, 16384, 3)
    const float* W       = (const float*)d_in[3];   // (64, 64)
    const float* bias    = (const float*)d_in[4];   // (64,)
    float* out = (float*)d_out;                     // (4, 16384, 64)

    prep_pos_kernel<<<(BATCH * NPTS + 255) / 256, 256>>>(pos);
    proj_kernel<<<(BATCH * NPTS) / PROJ_ROWS, 64>>>(feature, W, bias);

    dim3 grid(NUP / QPB, BATCH);
    knn_apply_kernel<<<grid, QPB>>>(pos_up, out);
}

// round 2
// speedup vs baseline: 1.1658x; 1.1658x over previous
#include <cuda_runtime.h>
#include <cuda_bf16.h>
#include <cfloat>

#define BATCH 4
#define NPTS 4096
#define NUP 16384
#define CDIM 64
#define EPSV 1e-6f

// Scratch (no cudaMalloc allowed)
__device__ float  g_G[BATCH * NPTS * CDIM];          // projected features F@W + b
__device__ float4 g_px4[BATCH * NPTS / 4];           // SoA pos: x
__device__ float4 g_py4[BATCH * NPTS / 4];           // y
__device__ float4 g_pz4[BATCH * NPTS / 4];           // z
__device__ float4 g_pw4[BATCH * NPTS / 4];           // |p|^2

// ---------------------------------------------------------------------------
// packed f32x2 helpers
// ---------------------------------------------------------------------------
__device__ __forceinline__ unsigned long long pack2(float lo, float hi) {
    unsigned long long r;
    asm("mov.b64 %0, {%1, %2};" : "=l"(r) : "f"(lo), "f"(hi));
    return r;
}
__device__ __forceinline__ void unpack2(unsigned long long v, float& lo, float& hi) {
    asm("mov.b64 {%0, %1}, %2;" : "=f"(lo), "=f"(hi) : "l"(v));
}
__device__ __forceinline__ unsigned long long fma2(unsigned long long a,
                                                   unsigned long long b,
                                                   unsigned long long c) {
    unsigned long long d;
    asm("fma.rn.f32x2 %0, %1, %2, %3;" : "=l"(d) : "l"(a), "l"(b), "l"(c));
    return d;
}

// ---------------------------------------------------------------------------
// Prep: pos AoS -> SoA with squared norm
// ---------------------------------------------------------------------------
__global__ void prep_pos_kernel(const float* __restrict__ pos) {
    int i = blockIdx.x * blockDim.x + threadIdx.x;
    if (i < BATCH * NPTS) {
        float x = pos[3 * i + 0];
        float y = pos[3 * i + 1];
        float z = pos[3 * i + 2];
        float n = x * x + y * y + z * z;
        ((float*)g_px4)[i] = x;
        ((float*)g_py4)[i] = y;
        ((float*)g_pz4)[i] = z;
        ((float*)g_pw4)[i] = n;
    }
}

// ---------------------------------------------------------------------------
// Projection: G = F @ W + b   (16384 x 64 x 64)
// ---------------------------------------------------------------------------
#define PROJ_ROWS 32

__global__ __launch_bounds__(64) void proj_kernel(
    const float* __restrict__ feature,
    const float* __restrict__ W,
    const float* __restrict__ bias)
{
    __shared__ float frow[PROJ_ROWS * CDIM];
    const int d = threadIdx.x;
    const int row0 = blockIdx.x * PROJ_ROWS;

    float wcol[CDIM];
#pragma unroll
    for (int k = 0; k < CDIM; k++) wcol[k] = __ldg(&W[k * CDIM + d]);
    const float bd = __ldg(&bias[d]);

    const float* fsrc = feature + (size_t)row0 * CDIM;
    for (int i = threadIdx.x; i < PROJ_ROWS * CDIM; i += 64)
        frow[i] = fsrc[i];
    __syncthreads();

    for (int r = 0; r < PROJ_ROWS; r++) {
        float a0 = bd, a1 = 0.f, a2 = 0.f, a3 = 0.f;
        const float* fr = &frow[r * CDIM];
#pragma unroll
        for (int k = 0; k < CDIM; k += 4) {
            a0 = fmaf(fr[k + 0], wcol[k + 0], a0);
            a1 = fmaf(fr[k + 1], wcol[k + 1], a1);
            a2 = fmaf(fr[k + 2], wcol[k + 2], a2);
            a3 = fmaf(fr[k + 3], wcol[k + 3], a3);
        }
        g_G[(size_t)(row0 + r) * CDIM + d] = (a0 + a1) + (a2 + a3);
    }
}

// ---------------------------------------------------------------------------
// 3-NN insert (rare path)
// ---------------------------------------------------------------------------
__device__ __forceinline__ void ins3(float s, int idx,
                                     float& d0, float& d1, float& d2,
                                     int& i0, int& i1, int& i2)
{
    if (s < d2) {
        if (s < d1) {
            d2 = d1; i2 = i1;
            if (s < d0) { d1 = d0; i1 = i0; d0 = s; i0 = idx; }
            else        { d1 = s;  i1 = idx; }
        } else {
            d2 = s; i2 = idx;
        }
    }
}

// ---------------------------------------------------------------------------
// Main: per-query brute-force 3-NN (8 candidates/iter, packed f32x2 math,
// branchless min-filter, rare branchy insert) + weighted gather of G.
// ---------------------------------------------------------------------------
#define QPB 128
#define CHUNK 2048     // candidates per smem tile (32 KB SoA)

__global__ __launch_bounds__(QPB) void knn_apply_kernel(
    const float* __restrict__ pos_up,
    float* __restrict__ out)
{
    __shared__ float4 sx[CHUNK / 4];
    __shared__ float4 sy[CHUNK / 4];
    __shared__ float4 sz[CHUNK / 4];
    __shared__ float4 sw[CHUNK / 4];

    const int b = blockIdx.y;
    const int q = blockIdx.x * QPB + threadIdx.x;

    const float* pu = pos_up + ((size_t)b * NUP + q) * 3;
    const float qx = pu[0], qy = pu[1], qz = pu[2];
    const float qn = qx * qx + qy * qy + qz * qz;
    const unsigned long long qx2p = pack2(-2.0f * qx, -2.0f * qx);
    const unsigned long long qy2p = pack2(-2.0f * qy, -2.0f * qy);
    const unsigned long long qz2p = pack2(-2.0f * qz, -2.0f * qz);

    float d0 = FLT_MAX, d1 = FLT_MAX, d2 = FLT_MAX;
    int   i0 = 0, i1 = 0, i2 = 0;

    const int base4 = b * (NPTS / 4);

    for (int c0 = 0; c0 < NPTS; c0 += CHUNK) {
        __syncthreads();
        {
            const int t0 = base4 + c0 / 4;
            for (int i = threadIdx.x; i < CHUNK / 4; i += QPB) {
                sx[i] = g_px4[t0 + i];
                sy[i] = g_py4[t0 + i];
                sz[i] = g_pz4[t0 + i];
                sw[i] = g_pw4[t0 + i];
            }
        }
        __syncthreads();

#pragma unroll 2
        for (int j = 0; j < CHUNK / 8; j++) {
            float4 X0 = sx[2 * j], X1 = sx[2 * j + 1];
            float4 Y0 = sy[2 * j], Y1 = sy[2 * j + 1];
            float4 Z0 = sz[2 * j], Z1 = sz[2 * j + 1];
            float4 W0 = sw[2 * j], W1 = sw[2 * j + 1];

            unsigned long long s01 = fma2(qx2p, pack2(X0.x, X0.y),
                                    fma2(qy2p, pack2(Y0.x, Y0.y),
                                    fma2(qz2p, pack2(Z0.x, Z0.y), pack2(W0.x, W0.y))));
            unsigned long long s23 = fma2(qx2p, pack2(X0.z, X0.w),
                                    fma2(qy2p, pack2(Y0.z, Y0.w),
                                    fma2(qz2p, pack2(Z0.z, Z0.w), pack2(W0.z, W0.w))));
            unsigned long long s45 = fma2(qx2p, pack2(X1.x, X1.y),
                                    fma2(qy2p, pack2(Y1.x, Y1.y),
                                    fma2(qz2p, pack2(Z1.x, Z1.y), pack2(W1.x, W1.y))));
            unsigned long long s67 = fma2(qx2p, pack2(X1.z, X1.w),
                                    fma2(qy2p, pack2(Y1.z, Y1.w),
                                    fma2(qz2p, pack2(Z1.z, Z1.w), pack2(W1.z, W1.w))));

            float s0, s1, s2, s3, s4, s5, s6, s7;
            unpack2(s01, s0, s1);
            unpack2(s23, s2, s3);
            unpack2(s45, s4, s5);
            unpack2(s67, s6, s7);

            float m = fminf(fminf(fminf(s0, s1), fminf(s2, s3)),
                            fminf(fminf(s4, s5), fminf(s6, s7)));

            if (m < d2) {
                const int idx = c0 + j * 8;
                ins3(s0, idx + 0, d0, d1, d2, i0, i1, i2);
                ins3(s1, idx + 1, d0, d1, d2, i0, i1, i2);
                ins3(s2, idx + 2, d0, d1, d2, i0, i1, i2);
                ins3(s3, idx + 3, d0, d1, d2, i0, i1, i2);
                ins3(s4, idx + 4, d0, d1, d2, i0, i1, i2);
                ins3(s5, idx + 5, d0, d1, d2, i0, i1, i2);
                ins3(s6, idx + 6, d0, d1, d2, i0, i1, i2);
                ins3(s7, idx + 7, d0, d1, d2, i0, i1, i2);
            }
        }
    }

    // weights: w = 1/(d^2 + eps), normalized  (add |q|^2 back)
    float w0 = 1.0f / ((d0 + qn) + EPSV);
    float w1 = 1.0f / ((d1 + qn) + EPSV);
    float w2 = 1.0f / ((d2 + qn) + EPSV);
    float inv = 1.0f / (w0 + w1 + w2);
    float wn0 = w0 * inv, wn1 = w1 * inv, wn2 = w2 * inv;

    const float4* G4 = reinterpret_cast<const float4*>(g_G);
    const float4* r0 = G4 + ((size_t)(b * NPTS + i0)) * (CDIM / 4);
    const float4* r1 = G4 + ((size_t)(b * NPTS + i1)) * (CDIM / 4);
    const float4* r2 = G4 + ((size_t)(b * NPTS + i2)) * (CDIM / 4);
    float4* out4 = reinterpret_cast<float4*>(out) + ((size_t)b * NUP + q) * (CDIM / 4);

#pragma unroll
    for (int t = 0; t < CDIM / 4; t++) {
        float4 a = __ldg(&r0[t]);
        float4 c = __ldg(&r1[t]);
        float4 e = __ldg(&r2[t]);
        float4 o;
        o.x = fmaxf(0.f, fmaf(wn0, a.x, fmaf(wn1, c.x, wn2 * e.x)));
        o.y = fmaxf(0.f, fmaf(wn0, a.y, fmaf(wn1, c.y, wn2 * e.y)));
        o.z = fmaxf(0.f, fmaf(wn0, a.z, fmaf(wn1, c.z, wn2 * e.z)));
        o.w = fmaxf(0.f, fmaf(wn0, a.w, fmaf(wn1, c.w, wn2 * e.w)));
        out4[t] = o;
    }
}

// ---------------------------------------------------------------------------
extern "C" void kernel_launch(void* const* d_in, const int* in_sizes, int n_in,
                              void* d_out, int out_size)
{
    const float* feature = (const float*)d_in[0];   // (4, 4096, 64)
    const float* pos     = (const float*)d_in[1];   // (4, 4096, 3)
    const float* pos_up  = (const float*)d_in[2];   // (4, 16384, 3)
    const float* W       = (const float*)d_in[3];   // (64, 64)
    const float* bias    = (const float*)d_in[4];   // (64,)
    float* out = (float*)d_out;                     // (4, 16384, 64)

    prep_pos_kernel<<<(BATCH * NPTS + 255) / 256, 256>>>(pos);
    proj_kernel<<<(BATCH * NPTS) / PROJ_ROWS, 64>>>(feature, W, bias);

    dim3 grid(NUP / QPB, BATCH);
    knn_apply_kernel<<<grid, QPB>>>(pos_up, out);
}